// round 2
// baseline (speedup 1.0000x reference)
#include <cuda_runtime.h>
#include <cuda_bf16.h>

// MotionLoss: per-row small-angle HTM chain + global MSE reduction.
// inputs  : [512,1024,18] f32   (d_in[0])
// targets : [512,1024, 7] f32   (d_in[1])
// out     : scalar f32 mean( ([err,disp] - targets[0:4])^2 )
//
// Single fused kernel: float4 staging -> padded smem -> per-row compute ->
// block partial -> last-block deterministic final reduce (no 2nd launch).

#define TPB 256
#define ROWS_PER_BLOCK 256
#define MAX_BLOCKS 8192

__device__ float g_partials[MAX_BLOCKS];
__device__ unsigned int g_ticket = 0;   // zero-init; last block resets it

__global__ __launch_bounds__(TPB) void motion_loss_fused(
    const float* __restrict__ in, const float* __restrict__ tgt,
    float* __restrict__ out, int n_rows)
{
    __shared__ float s_in[ROWS_PER_BLOCK * 19];   // pad 18 -> 19 (conflict-free reads)
    __shared__ float s_tg[ROWS_PER_BLOCK * 7];    // 7 coprime with 32

    const int row0 = blockIdx.x * ROWS_PER_BLOCK;
    const int rows = min(ROWS_PER_BLOCK, n_rows - row0);

    // ---- staging: coalesced float4 loads, scalar scatter into padded smem ----
    if (rows == ROWS_PER_BLOCK) {
        const float4* inb4 = (const float4*)(in + (size_t)row0 * 18);
        const int n4_in = ROWS_PER_BLOCK * 18 / 4;           // 1152
        for (int g4 = threadIdx.x; g4 < n4_in; g4 += TPB) {
            float4 v = inb4[g4];
            int idx = g4 * 4;
            int r = idx / 18;
            int c = idx - r * 18;
            float vv[4] = {v.x, v.y, v.z, v.w};
            #pragma unroll
            for (int j = 0; j < 4; ++j) {
                s_in[r * 19 + c] = vv[j];
                if (++c == 18) { c = 0; ++r; }
            }
        }
        const float4* tb4 = (const float4*)(tgt + (size_t)row0 * 7);
        const int n4_tg = ROWS_PER_BLOCK * 7 / 4;            // 448
        for (int g4 = threadIdx.x; g4 < n4_tg; g4 += TPB) {
            float4 v = tb4[g4];
            int idx = g4 * 4;
            float vv[4] = {v.x, v.y, v.z, v.w};
            #pragma unroll
            for (int j = 0; j < 4; ++j) s_tg[idx + j] = vv[j];
        }
    } else {
        // tail tile (not hit for 512*1024 rows, kept for safety)
        const float* inb = in + (size_t)row0 * 18;
        for (int g = threadIdx.x; g < rows * 18; g += TPB) {
            int r = g / 18, c = g - r * 18;
            s_in[r * 19 + c] = inb[g];
        }
        const float* tb = tgt + (size_t)row0 * 7;
        for (int g = threadIdx.x; g < rows * 7; g += TPB) s_tg[g] = tb[g];
    }
    __syncthreads();

    // ---- per-row compute ----
    float acc = 0.0f;
    if ((int)threadIdx.x < rows) {
        const float* v = &s_in[threadIdx.x * 19];
        const float* t = &s_tg[threadIdx.x * 7];

        const float p0 = v[0], p1 = v[1], p2 = v[2];
        const float s00 = v[3], s01 = v[4];
        const float s10 = v[5], s11 = v[6];
        const float s20 = v[7], s21 = v[8];
        const float exX = v[9],  eyX = v[10], ezX = v[11];
        const float exY = v[12], eyY = v[13], ezY = v[14];
        const float exZ = v[15], eyZ = v[16], ezZ = v[17];

        const float x = t[4], y = t[5], z = t[6];

        // w = MX * (MY * (MZ * P)), P=(x,y,z,1)
        float ax = x - ezZ * y + eyZ * z + s20;
        float ay = ezZ * x + y - exZ * z + s21;
        float az = -eyZ * x + exZ * y + z + p2;
        float bx = ax - ezY * ay + eyY * az + s10;
        float by = ezY * ax + ay - exY * az + p1;
        float bz = -eyY * ax + exY * ay + az + s11;
        float cx = bx - ezX * by + eyX * bz + p0;
        float cy = ezX * bx + by - exX * bz + s00;
        float cz = -eyX * bx + exX * by + bz + s01;

        const float m1 = cx - x;
        const float m2 = cy - y;
        const float m3 = cz - z;
        const float err = sqrtf(m1 * m1 + m2 * m2 + m3 * m3 + 1e-12f);

        const float d0 = err - t[0];
        const float d1 = m1 - t[1];
        const float d2 = m2 - t[2];
        const float d3 = m3 - t[3];
        acc = d0 * d0 + d1 * d1 + d2 * d2 + d3 * d3;
    }

    // ---- block reduction ----
    #pragma unroll
    for (int off = 16; off > 0; off >>= 1)
        acc += __shfl_down_sync(0xFFFFFFFFu, acc, off);

    __shared__ float s_warp[TPB / 32];
    const int lane = threadIdx.x & 31;
    const int wid  = threadIdx.x >> 5;
    if (lane == 0) s_warp[wid] = acc;
    __syncthreads();
    if (wid == 0) {
        float a = (lane < TPB / 32) ? s_warp[lane] : 0.0f;
        #pragma unroll
        for (int off = 4; off > 0; off >>= 1)
            a += __shfl_down_sync(0xFFFFFFFFu, a, off);
        if (lane == 0) g_partials[blockIdx.x] = a;
    }

    // ---- last-block-done: deterministic final reduce ----
    __shared__ bool s_last;
    __threadfence();
    if (threadIdx.x == 0) {
        unsigned int t = atomicAdd(&g_ticket, 1u);
        s_last = (t == gridDim.x - 1);
    }
    __syncthreads();
    if (!s_last) return;

    // fixed strided order per thread -> deterministic sum
    double sum = 0.0;
    for (int i = threadIdx.x; i < (int)gridDim.x; i += TPB)
        sum += (double)__ldcg(&g_partials[i]);

    __shared__ double s_fin[TPB];
    s_fin[threadIdx.x] = sum;
    __syncthreads();
    #pragma unroll
    for (int off = TPB / 2; off > 0; off >>= 1) {
        if ((int)threadIdx.x < off) s_fin[threadIdx.x] += s_fin[threadIdx.x + off];
        __syncthreads();
    }
    if (threadIdx.x == 0) {
        out[0] = (float)(s_fin[0] / ((double)n_rows * 4.0));
        g_ticket = 0;   // reset for next graph replay
    }
}

extern "C" void kernel_launch(void* const* d_in, const int* in_sizes, int n_in,
                              void* d_out, int out_size)
{
    const float* inputs  = (const float*)d_in[0];
    const float* targets = (const float*)d_in[1];
    float* out = (float*)d_out;

    const int n_rows = in_sizes[0] / 18;   // 524288
    const int n_blocks = (n_rows + ROWS_PER_BLOCK - 1) / ROWS_PER_BLOCK;  // 2048

    motion_loss_fused<<<n_blocks, TPB>>>(inputs, targets, out, n_rows);
}

// round 3
// speedup vs baseline: 1.0710x; 1.0710x over previous
#include <cuda_runtime.h>
#include <cuda_bf16.h>

// MotionLoss: per-row small-angle HTM chain + global MSE reduction.
// inputs  : [512,1024,18] f32   (d_in[0])
// targets : [512,1024, 7] f32   (d_in[1])
// out     : scalar f32 mean( ([err,disp] - targets[0:4])^2 )
//
// Flat float4 staging (conflict-free STS.128) -> per-row compute (2 rows/thread)
// -> block partial -> last-block deterministic final reduce.

#define TPB 256
#define RPB 512                      // rows per block
#define MAX_BLOCKS 8192

__device__ float g_partials[MAX_BLOCKS];
__device__ unsigned int g_ticket = 0;   // zero-init; last block resets it

__global__ __launch_bounds__(TPB) void motion_loss_fused(
    const float* __restrict__ in, const float* __restrict__ tgt,
    float* __restrict__ out, int n_rows)
{
    extern __shared__ float smem[];
    float* s_in = smem;               // [RPB*18] flat, unpadded
    float* s_tg = smem + RPB * 18;    // [RPB*7]  flat

    const int row0 = blockIdx.x * RPB;
    const int rows = min(RPB, n_rows - row0);

    // ---- staging: flat float4 loads + flat float4 stores (conflict-free) ----
    if (rows == RPB) {
        const float4* inb4 = (const float4*)(in + (size_t)row0 * 18);
        float4* s_in4 = (float4*)s_in;
        #pragma unroll
        for (int i = 0; i < RPB * 18 / 4 / TPB; ++i) {          // 9 iters
            int g = i * TPB + threadIdx.x;
            s_in4[g] = inb4[g];
        }
        const float4* tb4 = (const float4*)(tgt + (size_t)row0 * 7);
        float4* s_tg4 = (float4*)s_tg;
        for (int g = threadIdx.x; g < RPB * 7 / 4; g += TPB)    // 896 -> 3.5 iters
            s_tg4[g] = tb4[g];
    } else {
        const float* inb = in + (size_t)row0 * 18;
        for (int g = threadIdx.x; g < rows * 18; g += TPB) s_in[g] = inb[g];
        const float* tb = tgt + (size_t)row0 * 7;
        for (int g = threadIdx.x; g < rows * 7; g += TPB) s_tg[g] = tb[g];
    }
    __syncthreads();

    // ---- per-row compute: 2 rows per thread (independent -> ILP) ----
    float acc = 0.0f;
    #pragma unroll
    for (int rr = 0; rr < 2; ++rr) {
        const int r = threadIdx.x + rr * TPB;
        if (r < rows) {
            const float* v = &s_in[r * 18];
            const float* t = &s_tg[r * 7];

            const float p0 = v[0], p1 = v[1], p2 = v[2];
            const float s00 = v[3], s01 = v[4];
            const float s10 = v[5], s11 = v[6];
            const float s20 = v[7], s21 = v[8];
            const float exX = v[9],  eyX = v[10], ezX = v[11];
            const float exY = v[12], eyY = v[13], ezY = v[14];
            const float exZ = v[15], eyZ = v[16], ezZ = v[17];

            const float x = t[4], y = t[5], z = t[6];

            // w = MX * (MY * (MZ * P)), P=(x,y,z,1)
            float ax = x - ezZ * y + eyZ * z + s20;
            float ay = ezZ * x + y - exZ * z + s21;
            float az = -eyZ * x + exZ * y + z + p2;
            float bx = ax - ezY * ay + eyY * az + s10;
            float by = ezY * ax + ay - exY * az + p1;
            float bz = -eyY * ax + exY * ay + az + s11;
            float cx = bx - ezX * by + eyX * bz + p0;
            float cy = ezX * bx + by - exX * bz + s00;
            float cz = -eyX * bx + exX * by + bz + s01;

            const float m1 = cx - x;
            const float m2 = cy - y;
            const float m3 = cz - z;
            const float err = sqrtf(m1 * m1 + m2 * m2 + m3 * m3 + 1e-12f);

            const float d0 = err - t[0];
            const float d1 = m1 - t[1];
            const float d2 = m2 - t[2];
            const float d3 = m3 - t[3];
            acc += d0 * d0 + d1 * d1 + d2 * d2 + d3 * d3;
        }
    }

    // ---- block reduction ----
    #pragma unroll
    for (int off = 16; off > 0; off >>= 1)
        acc += __shfl_down_sync(0xFFFFFFFFu, acc, off);

    __shared__ float s_warp[TPB / 32];
    const int lane = threadIdx.x & 31;
    const int wid  = threadIdx.x >> 5;
    if (lane == 0) s_warp[wid] = acc;
    __syncthreads();
    if (wid == 0) {
        float a = (lane < TPB / 32) ? s_warp[lane] : 0.0f;
        #pragma unroll
        for (int off = 4; off > 0; off >>= 1)
            a += __shfl_down_sync(0xFFFFFFFFu, a, off);
        if (lane == 0) g_partials[blockIdx.x] = a;
    }

    // ---- last-block-done: deterministic final reduce ----
    __shared__ bool s_last;
    __threadfence();
    if (threadIdx.x == 0) {
        unsigned int tk = atomicAdd(&g_ticket, 1u);
        s_last = (tk == gridDim.x - 1);
    }
    __syncthreads();
    if (!s_last) return;

    double sum = 0.0;
    for (int i = threadIdx.x; i < (int)gridDim.x; i += TPB)
        sum += (double)__ldcg(&g_partials[i]);

    __shared__ double s_fin[TPB];
    s_fin[threadIdx.x] = sum;
    __syncthreads();
    #pragma unroll
    for (int off = TPB / 2; off > 0; off >>= 1) {
        if ((int)threadIdx.x < off) s_fin[threadIdx.x] += s_fin[threadIdx.x + off];
        __syncthreads();
    }
    if (threadIdx.x == 0) {
        out[0] = (float)(s_fin[0] / ((double)n_rows * 4.0));
        g_ticket = 0;   // reset for next graph replay
    }
}

extern "C" void kernel_launch(void* const* d_in, const int* in_sizes, int n_in,
                              void* d_out, int out_size)
{
    const float* inputs  = (const float*)d_in[0];
    const float* targets = (const float*)d_in[1];
    float* out = (float*)d_out;

    const int n_rows = in_sizes[0] / 18;   // 524288
    const int n_blocks = (n_rows + RPB - 1) / RPB;  // 1024
    const int smem_bytes = RPB * 25 * sizeof(float);  // 51200

    static bool attr_set = false;
    if (!attr_set) {
        cudaFuncSetAttribute(motion_loss_fused,
                             cudaFuncAttributeMaxDynamicSharedMemorySize,
                             smem_bytes);
        attr_set = true;
    }

    motion_loss_fused<<<n_blocks, TPB, smem_bytes>>>(inputs, targets, out, n_rows);
}

// round 4
// speedup vs baseline: 1.2635x; 1.1798x over previous
#include <cuda_runtime.h>
#include <cuda_bf16.h>
#include <cstdint>

// MotionLoss: per-row small-angle HTM chain + global MSE reduction.
// inputs  : [512,1024,18] f32   (d_in[0])
// targets : [512,1024, 7] f32   (d_in[1])
// out     : scalar f32
//
// Persistent kernel + 4-stage cp.async pipeline: copies stay in flight
// continuously (latency-bound fix for the ~2.7TB/s plateau seen in ncu).

#define TPB 128                 // threads per block == rows per tile
#define ROWS_TILE 128
#define NSTAGE 4
#define NBLK 592                // 4 CTAs/SM * 148 SMs

#define TILE_IN_F4   (ROWS_TILE * 18 / 4)          // 576 float4
#define TILE_TG_F4   (ROWS_TILE * 7 / 4)           // 224 float4
#define TILE_F4      (TILE_IN_F4 + TILE_TG_F4)     // 800 float4
#define TILE_FLOATS  (ROWS_TILE * 25)              // 3200 floats = 12.8KB

__device__ float g_partials[NBLK];
__device__ unsigned int g_ticket = 0;

__device__ __forceinline__ void cp_async16(uint32_t saddr, const void* gptr) {
    asm volatile("cp.async.cg.shared.global [%0], [%1], 16;" :: "r"(saddr), "l"(gptr));
}
__device__ __forceinline__ void cp_commit() {
    asm volatile("cp.async.commit_group;");
}
template <int N>
__device__ __forceinline__ void cp_wait() {
    asm volatile("cp.async.wait_group %0;" :: "n"(N));
}

__global__ __launch_bounds__(TPB) void motion_loss_pipe(
    const float* __restrict__ in, const float* __restrict__ tgt,
    float* __restrict__ out, int n_rows)
{
    extern __shared__ float smem[];   // NSTAGE * TILE_FLOATS
    const uint32_t smem_u32 = (uint32_t)__cvta_generic_to_shared(smem);

    const int T = n_rows / ROWS_TILE;            // full tiles (4096)
    const int bid = blockIdx.x;
    const int tid = threadIdx.x;

    // ---- issue helper: tile -> stage slot ----
    auto issue_tile = [&](int tile, int slot) {
        const float* inb = in  + (size_t)tile * (ROWS_TILE * 18);
        const float* tgb = tgt + (size_t)tile * (ROWS_TILE * 7);
        uint32_t sbase = smem_u32 + slot * (TILE_FLOATS * 4);
        #pragma unroll
        for (int i = 0; i < (TILE_F4 + TPB - 1) / TPB; ++i) {   // 7 iters
            int g = i * TPB + tid;
            if (g < TILE_F4) {
                const void* src = (g < TILE_IN_F4)
                    ? (const void*)(inb + g * 4)
                    : (const void*)(tgb + (g - TILE_IN_F4) * 4);
                cp_async16(sbase + g * 16, src);
            }
        }
    };

    // ---- prologue: fill NSTAGE-1 stages ----
    {
        int it = 0;
        for (int s = 0; s < NSTAGE - 1; ++s, ++it) {
            int tile = bid + it * NBLK;
            if (tile < T) issue_tile(tile, it % NSTAGE);
            cp_commit();
        }
    }

    // ---- main loop ----
    float acc = 0.0f;
    int it = 0;
    for (int tile = bid; tile < T; tile += NBLK, ++it) {
        cp_wait<NSTAGE - 2>();
        __syncthreads();

        const float* v = &smem[(it % NSTAGE) * TILE_FLOATS + tid * 18];
        const float* t = &smem[(it % NSTAGE) * TILE_FLOATS + ROWS_TILE * 18 + tid * 7];

        const float p0 = v[0], p1 = v[1], p2 = v[2];
        const float s00 = v[3], s01 = v[4];
        const float s10 = v[5], s11 = v[6];
        const float s20 = v[7], s21 = v[8];
        const float exX = v[9],  eyX = v[10], ezX = v[11];
        const float exY = v[12], eyY = v[13], ezY = v[14];
        const float exZ = v[15], eyZ = v[16], ezZ = v[17];

        const float x = t[4], y = t[5], z = t[6];

        // w = MX * (MY * (MZ * P)), P=(x,y,z,1)
        float ax = x - ezZ * y + eyZ * z + s20;
        float ay = ezZ * x + y - exZ * z + s21;
        float az = -eyZ * x + exZ * y + z + p2;
        float bx = ax - ezY * ay + eyY * az + s10;
        float by = ezY * ax + ay - exY * az + p1;
        float bz = -eyY * ax + exY * ay + az + s11;
        float cx = bx - ezX * by + eyX * bz + p0;
        float cy = ezX * bx + by - exX * bz + s00;
        float cz = -eyX * bx + exX * by + bz + s01;

        const float m1 = cx - x;
        const float m2 = cy - y;
        const float m3 = cz - z;
        const float err = sqrtf(m1 * m1 + m2 * m2 + m3 * m3 + 1e-12f);

        const float d0 = err - t[0];
        const float d1 = m1 - t[1];
        const float d2 = m2 - t[2];
        const float d3 = m3 - t[3];
        acc += d0 * d0 + d1 * d1 + d2 * d2 + d3 * d3;

        __syncthreads();   // all threads done reading before slot reuse

        // issue tile it + NSTAGE-1 into its slot
        int nxt_it = it + NSTAGE - 1;
        int nxt_tile = bid + nxt_it * NBLK;
        if (nxt_tile < T) issue_tile(nxt_tile, nxt_it % NSTAGE);
        cp_commit();
    }
    cp_wait<0>();
    __syncthreads();

    // ---- block reduction (deterministic per-block) ----
    #pragma unroll
    for (int off = 16; off > 0; off >>= 1)
        acc += __shfl_down_sync(0xFFFFFFFFu, acc, off);

    __shared__ float s_warp[TPB / 32];
    const int lane = tid & 31;
    const int wid  = tid >> 5;
    if (lane == 0) s_warp[wid] = acc;
    __syncthreads();
    if (wid == 0) {
        float a = (lane < TPB / 32) ? s_warp[lane] : 0.0f;
        #pragma unroll
        for (int off = 2; off > 0; off >>= 1)
            a += __shfl_down_sync(0xFFFFFFFFu, a, off);
        if (lane == 0) g_partials[bid] = a;
    }

    // ---- last-block-done: deterministic final reduce ----
    __shared__ bool s_last;
    __threadfence();
    if (tid == 0) {
        unsigned int tk = atomicAdd(&g_ticket, 1u);
        s_last = (tk == gridDim.x - 1);
    }
    __syncthreads();
    if (!s_last) return;

    double sum = 0.0;
    for (int i = tid; i < (int)gridDim.x; i += TPB)
        sum += (double)__ldcg(&g_partials[i]);

    // remainder rows not covered by full tiles (none for 512*1024, kept for safety)
    if (tid == 0) {
        for (int r = T * ROWS_TILE; r < n_rows; ++r) {
            const float* v = in + (size_t)r * 18;
            const float* t = tgt + (size_t)r * 7;
            float x = t[4], y = t[5], z = t[6];
            float ax = x - v[17]*y + v[16]*z + v[7];
            float ay = v[17]*x + y - v[15]*z + v[8];
            float az = -v[16]*x + v[15]*y + z + v[2];
            float bx = ax - v[14]*ay + v[13]*az + v[5];
            float by = v[14]*ax + ay - v[12]*az + v[1];
            float bz = -v[13]*ax + v[12]*ay + az + v[6];
            float cx = bx - v[11]*by + v[10]*bz + v[0];
            float cy = v[11]*bx + by - v[9]*bz + v[3];
            float cz = -v[10]*bx + v[9]*by + bz + v[4];
            float m1 = cx - x, m2 = cy - y, m3 = cz - z;
            float err = sqrtf(m1*m1 + m2*m2 + m3*m3 + 1e-12f);
            float d0 = err - t[0], d1 = m1 - t[1], d2 = m2 - t[2], d3 = m3 - t[3];
            sum += (double)(d0*d0 + d1*d1 + d2*d2 + d3*d3);
        }
    }

    __shared__ double s_fin[TPB];
    s_fin[tid] = sum;
    __syncthreads();
    #pragma unroll
    for (int off = TPB / 2; off > 0; off >>= 1) {
        if (tid < off) s_fin[tid] += s_fin[tid + off];
        __syncthreads();
    }
    if (tid == 0) {
        out[0] = (float)(s_fin[0] / ((double)n_rows * 4.0));
        g_ticket = 0;   // reset for next graph replay
    }
}

extern "C" void kernel_launch(void* const* d_in, const int* in_sizes, int n_in,
                              void* d_out, int out_size)
{
    const float* inputs  = (const float*)d_in[0];
    const float* targets = (const float*)d_in[1];
    float* out = (float*)d_out;

    const int n_rows = in_sizes[0] / 18;                   // 524288
    const int smem_bytes = NSTAGE * TILE_FLOATS * 4;       // 51200

    static bool attr_set = false;
    if (!attr_set) {
        cudaFuncSetAttribute(motion_loss_pipe,
                             cudaFuncAttributeMaxDynamicSharedMemorySize,
                             smem_bytes);
        attr_set = true;
    }

    motion_loss_pipe<<<NBLK, TPB, smem_bytes>>>(inputs, targets, out, n_rows);
}

// round 5
// speedup vs baseline: 1.3290x; 1.0518x over previous
#include <cuda_runtime.h>
#include <cuda_bf16.h>
#include <cstdint>

// MotionLoss: per-row small-angle HTM chain + global MSE reduction.
// inputs  : [512,1024,18] f32   (d_in[0])
// targets : [512,1024, 7] f32   (d_in[1])
// out     : scalar f32
//
// Persistent kernel + 4-stage TMA-bulk (cp.async.bulk + mbarrier) pipeline.
// TMA engine tracks the transfers -> not limited by per-thread LSU/MSHR
// outstanding-request caps that throttled the cp.async version (DRAM 42%).

#define TPB 256
#define ROWS_TILE 256
#define NSTAGE 4
#define NBLK 296                       // 2 CTAs/SM * 148 SMs

#define TILE_IN_FLOATS (ROWS_TILE * 18)        // 4608
#define TILE_TG_FLOATS (ROWS_TILE * 7)         // 1792
#define TILE_FLOATS    (ROWS_TILE * 25)        // 6400
#define TILE_IN_BYTES  (TILE_IN_FLOATS * 4)    // 18432
#define TILE_TG_BYTES  (TILE_TG_FLOATS * 4)    // 7168
#define TILE_BYTES     (TILE_FLOATS * 4)       // 25600

__device__ float g_partials[NBLK];
__device__ unsigned int g_ticket = 0;

__device__ __forceinline__ uint32_t smem_u32(const void* p) {
    return (uint32_t)__cvta_generic_to_shared(p);
}
__device__ __forceinline__ void mbar_init(uint32_t addr, uint32_t count) {
    asm volatile("mbarrier.init.shared.b64 [%0], %1;" :: "r"(addr), "r"(count) : "memory");
}
__device__ __forceinline__ void mbar_expect_tx(uint32_t addr, uint32_t bytes) {
    asm volatile("mbarrier.arrive.expect_tx.shared.b64 _, [%0], %1;"
                 :: "r"(addr), "r"(bytes) : "memory");
}
__device__ __forceinline__ void bulk_g2s(uint32_t dst, const void* src,
                                         uint32_t bytes, uint32_t mbar) {
    asm volatile(
        "cp.async.bulk.shared::cluster.global.mbarrier::complete_tx::bytes "
        "[%0], [%1], %2, [%3];"
        :: "r"(dst), "l"(src), "r"(bytes), "r"(mbar) : "memory");
}
__device__ __forceinline__ void mbar_wait(uint32_t addr, uint32_t parity) {
    uint32_t done;
    asm volatile(
        "{\n\t.reg .pred p;\n\t"
        "mbarrier.try_wait.parity.acquire.cta.shared::cta.b64 p, [%1], %2;\n\t"
        "selp.b32 %0, 1, 0, p;\n\t}"
        : "=r"(done) : "r"(addr), "r"(parity) : "memory");
    if (!done) {
        asm volatile(
            "{\n\t.reg .pred P1;\n\t"
            "WAIT_LOOP_%=:\n\t"
            "mbarrier.try_wait.parity.acquire.cta.shared::cta.b64 P1, [%0], %1, 0x989680;\n\t"
            "@P1 bra.uni WAIT_DONE_%=;\n\t"
            "bra.uni WAIT_LOOP_%=;\n\t"
            "WAIT_DONE_%=:\n\t}"
            :: "r"(addr), "r"(parity) : "memory");
    }
}

__global__ __launch_bounds__(TPB) void motion_loss_tma(
    const float* __restrict__ in, const float* __restrict__ tgt,
    float* __restrict__ out, int n_rows)
{
    extern __shared__ float smem[];                 // [NSTAGE*TILE_FLOATS] + barriers
    uint64_t* mbar = (uint64_t*)(smem + NSTAGE * TILE_FLOATS);

    const int T = n_rows / ROWS_TILE;               // 2048 full tiles
    const int bid = blockIdx.x;
    const int tid = threadIdx.x;

    // ---- init barriers ----
    if (tid == 0) {
        #pragma unroll
        for (int s = 0; s < NSTAGE; ++s) mbar_init(smem_u32(&mbar[s]), 1);
    }
    asm volatile("fence.proxy.async.shared::cta;" ::: "memory");
    __syncthreads();

    auto issue_tile = [&](int tile, int slot) {     // tid==0 only
        uint32_t bar = smem_u32(&mbar[slot]);
        uint32_t dst = smem_u32(smem + slot * TILE_FLOATS);
        mbar_expect_tx(bar, TILE_BYTES);
        bulk_g2s(dst, in + (size_t)tile * TILE_IN_FLOATS, TILE_IN_BYTES, bar);
        bulk_g2s(dst + TILE_IN_BYTES, tgt + (size_t)tile * TILE_TG_FLOATS,
                 TILE_TG_BYTES, bar);
    };

    // ---- prologue: fill NSTAGE-1 stages ----
    if (tid == 0) {
        for (int it = 0; it < NSTAGE - 1; ++it) {
            int tile = bid + it * NBLK;
            if (tile < T) issue_tile(tile, it);
        }
    }

    // ---- main loop ----
    float acc = 0.0f;
    int it = 0;
    for (int tile = bid; tile < T; tile += NBLK, ++it) {
        const int slot = it % NSTAGE;
        const uint32_t parity = (uint32_t)((it / NSTAGE) & 1);
        mbar_wait(smem_u32(&mbar[slot]), parity);

        const float* v = &smem[slot * TILE_FLOATS + tid * 18];
        const float* t = &smem[slot * TILE_FLOATS + TILE_IN_FLOATS + tid * 7];

        const float p0 = v[0], p1 = v[1], p2 = v[2];
        const float s00 = v[3], s01 = v[4];
        const float s10 = v[5], s11 = v[6];
        const float s20 = v[7], s21 = v[8];
        const float exX = v[9],  eyX = v[10], ezX = v[11];
        const float exY = v[12], eyY = v[13], ezY = v[14];
        const float exZ = v[15], eyZ = v[16], ezZ = v[17];

        const float x = t[4], y = t[5], z = t[6];

        // w = MX * (MY * (MZ * P)), P=(x,y,z,1)
        float ax = x - ezZ * y + eyZ * z + s20;
        float ay = ezZ * x + y - exZ * z + s21;
        float az = -eyZ * x + exZ * y + z + p2;
        float bx = ax - ezY * ay + eyY * az + s10;
        float by = ezY * ax + ay - exY * az + p1;
        float bz = -eyY * ax + exY * ay + az + s11;
        float cx = bx - ezX * by + eyX * bz + p0;
        float cy = ezX * bx + by - exX * bz + s00;
        float cz = -eyX * bx + exX * by + bz + s01;

        const float m1 = cx - x;
        const float m2 = cy - y;
        const float m3 = cz - z;
        const float err = sqrtf(m1 * m1 + m2 * m2 + m3 * m3 + 1e-12f);

        const float d0 = err - t[0];
        const float d1 = m1 - t[1];
        const float d2 = m2 - t[2];
        const float d3 = m3 - t[3];
        acc += d0 * d0 + d1 * d1 + d2 * d2 + d3 * d3;

        __syncthreads();            // all readers done before slot reuse

        if (tid == 0) {
            int nxt_it = it + NSTAGE - 1;
            int nxt_tile = bid + nxt_it * NBLK;
            if (nxt_tile < T) issue_tile(nxt_tile, nxt_it % NSTAGE);
        }
    }

    // ---- block reduction (deterministic) ----
    #pragma unroll
    for (int off = 16; off > 0; off >>= 1)
        acc += __shfl_down_sync(0xFFFFFFFFu, acc, off);

    __shared__ float s_warp[TPB / 32];
    const int lane = tid & 31;
    const int wid  = tid >> 5;
    if (lane == 0) s_warp[wid] = acc;
    __syncthreads();
    if (wid == 0) {
        float a = (lane < TPB / 32) ? s_warp[lane] : 0.0f;
        #pragma unroll
        for (int off = 4; off > 0; off >>= 1)
            a += __shfl_down_sync(0xFFFFFFFFu, a, off);
        if (lane == 0) g_partials[bid] = a;
    }

    // ---- last-block-done final reduce ----
    __shared__ bool s_last;
    __threadfence();
    if (tid == 0) {
        unsigned int tk = atomicAdd(&g_ticket, 1u);
        s_last = (tk == gridDim.x - 1);
    }
    __syncthreads();
    if (!s_last) return;

    double sum = 0.0;
    for (int i = tid; i < (int)gridDim.x; i += TPB)
        sum += (double)__ldcg(&g_partials[i]);

    if (tid == 0) {   // remainder rows (none for 512*1024; safety)
        for (int r = T * ROWS_TILE; r < n_rows; ++r) {
            const float* v = in + (size_t)r * 18;
            const float* t = tgt + (size_t)r * 7;
            float x = t[4], y = t[5], z = t[6];
            float ax = x - v[17]*y + v[16]*z + v[7];
            float ay = v[17]*x + y - v[15]*z + v[8];
            float az = -v[16]*x + v[15]*y + z + v[2];
            float bx = ax - v[14]*ay + v[13]*az + v[5];
            float by = v[14]*ax + ay - v[12]*az + v[1];
            float bz = -v[13]*ax + v[12]*ay + az + v[6];
            float cx = bx - v[11]*by + v[10]*bz + v[0];
            float cy = v[11]*bx + by - v[9]*bz + v[3];
            float cz = -v[10]*bx + v[9]*by + bz + v[4];
            float m1 = cx - x, m2 = cy - y, m3 = cz - z;
            float err = sqrtf(m1*m1 + m2*m2 + m3*m3 + 1e-12f);
            float d0 = err - t[0], d1 = m1 - t[1], d2 = m2 - t[2], d3 = m3 - t[3];
            sum += (double)(d0*d0 + d1*d1 + d2*d2 + d3*d3);
        }
    }

    __shared__ double s_fin[TPB];
    s_fin[tid] = sum;
    __syncthreads();
    #pragma unroll
    for (int off = TPB / 2; off > 0; off >>= 1) {
        if (tid < off) s_fin[tid] += s_fin[tid + off];
        __syncthreads();
    }
    if (tid == 0) {
        out[0] = (float)(s_fin[0] / ((double)n_rows * 4.0));
        g_ticket = 0;   // reset for next graph replay
    }
}

extern "C" void kernel_launch(void* const* d_in, const int* in_sizes, int n_in,
                              void* d_out, int out_size)
{
    const float* inputs  = (const float*)d_in[0];
    const float* targets = (const float*)d_in[1];
    float* out = (float*)d_out;

    const int n_rows = in_sizes[0] / 18;                       // 524288
    const int smem_bytes = NSTAGE * TILE_BYTES + NSTAGE * 8;   // 102432

    static bool attr_set = false;
    if (!attr_set) {
        cudaFuncSetAttribute(motion_loss_tma,
                             cudaFuncAttributeMaxDynamicSharedMemorySize,
                             smem_bytes);
        attr_set = true;
    }

    motion_loss_tma<<<NBLK, TPB, smem_bytes>>>(inputs, targets, out, n_rows);
}